// round 15
// baseline (speedup 1.0000x reference)
#include <cuda_runtime.h>
#include <cuda_fp16.h>
#include <cstdint>

// Problem constants
#define BB 4
#define SS 2048
#define DD 1024
#define MM 4096
#define LL 4
#define ROWS (BB*SS)          // 8192
#define NEG_INF __int_as_float(0xff800000)

// GEMM tiling: 128x256 block tile, BK=64, 256 threads (8 warps 2x4, warp 64x64)
// fp16 split: A hi-only, B hi(+optional lo, template BLO).
#define SA 72                 // smem row stride (fp16) = 144B, conflict-free
#define ATILE 18432           // 128*SA*2
#define BTILE 36864           // 256*SA*2
#define STAGE (ATILE + 2*BTILE)     // 92160
#define NSTG 2
#define SMEM_DYN (NSTG*STAGE)       // 184320

// ---------------- scratch (device globals; no allocation allowed) ----------
__device__ __half g_hH[ROWS*DD];
__device__ __half g_qH[ROWS*DD];
__device__ __half g_kH[ROWS*DD],  g_kL[ROWS*DD];
__device__ __half g_vTH[ROWS*DD], g_vTL[ROWS*DD];
__device__ __half g_scH[BB*SS*SS];
__device__ __half g_midH[(long long)ROWS*MM];
__device__ __half g_wqkvH[3*DD*DD], g_wqkvL[3*DD*DD];
__device__ __half g_w1H[LL*DD*MM];                 // FFN1 weights: hi only (1-MMA)
__device__ __half g_w2H[LL*DD*MM], g_w2L[LL*DD*MM];
__device__ float g_v[ROWS*DD];
__device__ float g_sc[BB*SS*SS];
__device__ int   g_is32;

// ---------------------------------------------------------------------------
__global__ void detect_kernel(const void* __restrict__ x) {
    const long long* p = (const long long*)x;
    int bad = 0;
    for (int i = threadIdx.x; i < 4096; i += 256) {
        long long v = p[i];
        if (v < 0 || v >= 32000) bad = 1;
    }
    bad = __syncthreads_or(bad);
    if (threadIdx.x == 0) g_is32 = bad;
}

// h = emb[x] + pos -> fp16 (hi only; h is always an A operand)
__global__ __launch_bounds__(256) void embed_kernel(
    const void* __restrict__ x, const float* __restrict__ emb,
    const float* __restrict__ pos, __half* __restrict__ hH)
{
    int row = blockIdx.x;
    int s = row & (SS - 1);
    long long tok;
    if (g_is32) tok = ((const int*)x)[row];
    else        tok = ((const long long*)x)[row];
    int t = threadIdx.x;
    float4 a = ((const float4*)(emb + tok * (long long)DD))[t];
    float4 b = ((const float4*)(pos + (long long)s * DD))[t];
    __half h4[4];
    h4[0] = __float2half_rn(a.x + b.x);
    h4[1] = __float2half_rn(a.y + b.y);
    h4[2] = __float2half_rn(a.z + b.z);
    h4[3] = __float2half_rn(a.w + b.w);
    *(uint2*)(hH + (long long)row * DD + 4 * t) = *(uint2*)h4;
}

// ---------------------------------------------------------------------------
// Transpose + split: fp32 [R,C] row-major -> fp16 hi (+lo if wlo) [C,R].
__global__ __launch_bounds__(256) void transcvt_kernel(
    const float* __restrict__ in,
    __half* __restrict__ oH, __half* __restrict__ oL,
    int R, int C, long long si, long long so, int wlo)
{
    __shared__ float t[32][33];
    in += (long long)blockIdx.z * si;
    oH += (long long)blockIdx.z * so;
    oL += (long long)blockIdx.z * so;
    int x  = blockIdx.x * 32 + threadIdx.x;
    int y0 = blockIdx.y * 32 + threadIdx.y;
    #pragma unroll
    for (int j = 0; j < 32; j += 8)
        t[threadIdx.y + j][threadIdx.x] = in[(long long)(y0 + j) * C + x];
    __syncthreads();
    int x2 = blockIdx.y * 32 + threadIdx.x;
    int y2 = blockIdx.x * 32 + threadIdx.y;
    #pragma unroll
    for (int j = 0; j < 32; j += 8) {
        float v = t[threadIdx.x][threadIdx.y + j];
        __half h = __float2half_rn(v);
        oH[(long long)(y2 + j) * R + x2] = h;
        if (wlo) {
            __half l = __float2half_rn(v - __half2float(h));
            oL[(long long)(y2 + j) * R + x2] = l;
        }
    }
}

// QKV weight transpose+split in ONE launch (z selects wq/wk/wv).
__global__ __launch_bounds__(256) void qkvw_transcvt_kernel(
    const float* __restrict__ wq, const float* __restrict__ wk,
    const float* __restrict__ wv,
    __half* __restrict__ oH, __half* __restrict__ oL)
{
    __shared__ float t[32][33];
    const float* in = (blockIdx.z == 0) ? wq : (blockIdx.z == 1) ? wk : wv;
    oH += (long long)blockIdx.z * DD * DD;
    oL += (long long)blockIdx.z * DD * DD;
    int x  = blockIdx.x * 32 + threadIdx.x;
    int y0 = blockIdx.y * 32 + threadIdx.y;
    #pragma unroll
    for (int j = 0; j < 32; j += 8)
        t[threadIdx.y + j][threadIdx.x] = in[(long long)(y0 + j) * DD + x];
    __syncthreads();
    int x2 = blockIdx.y * 32 + threadIdx.x;
    int y2 = blockIdx.x * 32 + threadIdx.y;
    #pragma unroll
    for (int j = 0; j < 32; j += 8) {
        float v = t[threadIdx.x][threadIdx.y + j];
        __half h = __float2half_rn(v);
        __half l = __float2half_rn(v - __half2float(h));
        oH[(long long)(y2 + j) * DD + x2] = h;
        oL[(long long)(y2 + j) * DD + x2] = l;
    }
}

// ---------------------------------------------------------------------------
__device__ __forceinline__ unsigned cvta_s(const void* p) {
    return (unsigned)__cvta_generic_to_shared(p);
}
__device__ __forceinline__ void cpa16(unsigned s, const void* g) {
    asm volatile("cp.async.cg.shared.global [%0], [%1], 16;" :: "r"(s), "l"(g));
}
__device__ __forceinline__ void ldsm4(unsigned addr, unsigned* r) {
    asm volatile("ldmatrix.sync.aligned.m8n8.x4.shared.b16 {%0,%1,%2,%3},[%4];"
                 : "=r"(r[0]), "=r"(r[1]), "=r"(r[2]), "=r"(r[3]) : "r"(addr));
}
__device__ __forceinline__ void mma_f16(float* c, const unsigned* a,
                                        unsigned b0, unsigned b1) {
    asm volatile(
        "mma.sync.aligned.m16n8k16.row.col.f32.f16.f16.f32 "
        "{%0,%1,%2,%3},{%4,%5,%6,%7},{%8,%9},{%0,%1,%2,%3};"
        : "+f"(c[0]), "+f"(c[1]), "+f"(c[2]), "+f"(c[3])
        : "r"(a[0]), "r"(a[1]), "r"(a[2]), "r"(a[3]), "r"(b0), "r"(b1));
}

// Inner MMA block: ah*bh (+ ah*bl when BLO). BLO is a constexpr in scope.
// ahc = current ks A fragments [4][4].
#define MMA_BLOCK(acc, ahc, bh_cur, bl_cur)                                   \
    {                                                                         \
        _Pragma("unroll")                                                     \
        for (int half = 0; half < 2; half++)                                  \
            _Pragma("unroll")                                                 \
            for (int mi = 0; mi < 4; mi++)                                    \
                mma_f16(acc[mi][np * 2 + half], ahc[mi],                      \
                        bh_cur[half * 2], bh_cur[half * 2 + 1]);              \
        if (BLO) {                                                            \
            _Pragma("unroll")                                                 \
            for (int half = 0; half < 2; half++)                              \
                _Pragma("unroll")                                             \
                for (int mi = 0; mi < 4; mi++)                                \
                    mma_f16(acc[mi][np * 2 + half], ahc[mi],                  \
                            bl_cur[half * 2], bl_cur[half * 2 + 1]);          \
        }                                                                     \
    }

// Shared mainloop, BK=64, 2-stage gmem pipeline (round-12 scheme) with
// A-fragment double-buffering: ks=0 A frags hoisted before the ks loop; the
// 4 A-ldsm for ks+1 are spread one-per-np through ks's MMA blocks.
#define GEMM_MAINLOOP(NCv, CH0v)                                              \
    auto load_stage = [&](int s, int k0) {                                    \
        unsigned sb = cvta_s(smem + s * STAGE);                               \
        int rr = tid >> 3, cc = tid & 7;                                      \
        _Pragma("unroll")                                                     \
        for (int i = 0; i < 4; i++) {                                         \
            int r = rr + 32 * i;                                              \
            long long go = (long long)r * K + k0 + 8 * cc;                    \
            unsigned so = (unsigned)(r * 144 + cc * 16);                      \
            cpa16(sb + so, AtH + go);                                         \
        }                                                                     \
        _Pragma("unroll")                                                     \
        for (int i = 0; i < 8; i++) {                                         \
            int r = rr + 32 * i;                                              \
            long long go = (long long)r * K + k0 + 8 * cc;                    \
            unsigned so = (unsigned)(r * 144 + cc * 16);                      \
            cpa16(sb + ATILE + so, BtH + go);                                 \
            if (BLO) cpa16(sb + ATILE + BTILE + so, BtL + go);                \
        }                                                                     \
        asm volatile("cp.async.commit_group;");                               \
    };                                                                        \
    load_stage(0, (CH0v) * 64);                                               \
    for (int ch = (CH0v); ch < (NCv); ch++) {                                 \
        const int s = (ch - (CH0v)) & 1;                                      \
        asm volatile("cp.async.wait_group 0;");                               \
        __syncthreads();                                                      \
        if (ch + 1 < (NCv)) load_stage(s ^ 1, (ch + 1) * 64);                 \
        const __half* As_hi = (const __half*)(smem + s * STAGE);              \
        const __half* Bs_hi = (const __half*)(smem + s * STAGE + ATILE);      \
        const __half* Bs_lo = (const __half*)(smem + s * STAGE + ATILE + BTILE);\
        const int g = lane >> 3;                                              \
        const int brow_base = n_off + ((g >> 1) << 3) + (lane & 7);           \
        const int a_kel0 = (lane >> 4) << 3;                                  \
        unsigned ah[2][4][4];                                                 \
        _Pragma("unroll")                                                     \
        for (int mi = 0; mi < 4; mi++) {                                      \
            int rrow = m_off + mi * 16 + (lane & 15);                         \
            ldsm4(cvta_s(As_hi + rrow * SA + a_kel0), ah[0][mi]);             \
        }                                                                     \
        _Pragma("unroll")                                                     \
        for (int ks = 0; ks < 4; ks++) {                                      \
            const int abuf = ks & 1;                                          \
            const int kel_b = ks * 16 + ((g & 1) << 3);                       \
            unsigned bh[2][4], bl[2][4];                                      \
            ldsm4(cvta_s(Bs_hi + brow_base * SA + kel_b), bh[0]);             \
            if (BLO) ldsm4(cvta_s(Bs_lo + brow_base * SA + kel_b), bl[0]);    \
            _Pragma("unroll")                                                 \
            for (int np = 0; np < 4; np++) {                                  \
                const int cur = np & 1, nxt = cur ^ 1;                        \
                if (np < 3) {                                                 \
                    ldsm4(cvta_s(Bs_hi + (brow_base + (np + 1) * 16) * SA + kel_b), bh[nxt]);\
                    if (BLO) ldsm4(cvta_s(Bs_lo + (brow_base + (np + 1) * 16) * SA + kel_b), bl[nxt]);\
                }                                                             \
                if (ks < 3) {                                                 \
                    int rrow = m_off + np * 16 + (lane & 15);                 \
                    int kel  = a_kel0 + (ks + 1) * 16;                        \
                    ldsm4(cvta_s(As_hi + rrow * SA + kel), ah[abuf ^ 1][np]); \
                }                                                             \
                MMA_BLOCK(acc, ah[abuf], bh[cur], bl[cur])                    \
            }                                                                 \
        }                                                                     \
    }

// ---------------------------------------------------------------------------
// HMMA GEMM, TN: C[M,N] = A[M,K] @ B[N,K]^T. 128x256 tile, 256 threads,
// warp tile 64x64. A fp16 (hi only), B fp16 hi (+lo when BLO=1).
// EPI:  0 = +bias, 1 = +bias(+opt null)+relu, 2 = scale + anti-causal mask
// OUTM: 0 = fp32 C, 1 = fp16 hi-only (Chi)
// TRIM: 1 = start K loop at row0 (A cols exactly zero for k < row0)
// BLO:  1 = 2-MMA split (B hi+lo), 0 = 1-MMA plain fp16 B
template<int EPI, int OUTM, int TRIM, int BLO>
__global__ __launch_bounds__(256, 1) void hmma_gemm(
    const __half* __restrict__ Ahi,
    const __half* __restrict__ Bhi, const __half* __restrict__ Blo,
    const float* __restrict__ bias, float* __restrict__ C,
    __half* __restrict__ Chi,
    int M, int N, int K,
    long long sA, long long sB, long long sC, float scale)
{
    extern __shared__ __align__(128) char smem[];

    const long long zC = (long long)blockIdx.z * sC;
    const int tid  = threadIdx.x;
    const int lane = tid & 31;
    const int wid  = tid >> 5;
    const int row0 = blockIdx.y * 128;
    const int col0 = blockIdx.x * 256;
    const int m_off = (wid & 1) * 64;
    const int n_off = (wid >> 1) * 64;

    if (EPI == 2 && col0 + 256 <= row0) {
        #pragma unroll
        for (int mi = 0; mi < 4; mi++) {
            #pragma unroll
            for (int ni = 0; ni < 8; ni++) {
                int r_base = row0 + m_off + mi * 16 + (lane >> 2);
                int c      = col0 + n_off + ni * 8 + 2 * (lane & 3);
                #pragma unroll
                for (int hh = 0; hh < 2; hh++) {
                    long long off = zC + (long long)(r_base + hh * 8) * N + c;
                    *(float2*)(C + off) = make_float2(NEG_INF, NEG_INF);
                }
            }
        }
        return;
    }

    const long long zA = (long long)blockIdx.z * sA;
    const long long zB = (long long)blockIdx.z * sB;
    const __half* AtH = Ahi + zA + (long long)row0 * K;
    const __half* BtH = Bhi + zB + (long long)col0 * K;
    const __half* BtL = Blo + zB + (long long)col0 * K;

    float acc[4][8][4];
    #pragma unroll
    for (int mi = 0; mi < 4; mi++)
        #pragma unroll
        for (int ni = 0; ni < 8; ni++)
            #pragma unroll
            for (int j = 0; j < 4; j++) acc[mi][ni][j] = 0.f;

    const int NC  = K / 64;
    const int ch0 = TRIM ? (row0 >> 6) : 0;

    GEMM_MAINLOOP(NC, ch0)

    const bool has_bias = (bias != nullptr);
    #pragma unroll
    for (int mi = 0; mi < 4; mi++) {
        #pragma unroll
        for (int ni = 0; ni < 8; ni++) {
            int r_base = row0 + m_off + mi * 16 + (lane >> 2);
            int c      = col0 + n_off + ni * 8 + 2 * (lane & 3);
            #pragma unroll
            for (int hh = 0; hh < 2; hh++) {
                int r = r_base + hh * 8;
                float v0 = acc[mi][ni][2 * hh];
                float v1 = acc[mi][ni][2 * hh + 1];
                if (EPI == 2) {
                    v0 *= scale; v1 *= scale;
                    if (c < r)     v0 = NEG_INF;
                    if (c + 1 < r) v1 = NEG_INF;
                } else {
                    if (has_bias) { v0 += bias[c]; v1 += bias[c + 1]; }
                    if (EPI == 1) { v0 = fmaxf(v0, 0.f); v1 = fmaxf(v1, 0.f); }
                }
                long long off = zC + (long long)r * N + c;
                if (OUTM == 0) {
                    *(float2*)(C + off) = make_float2(v0, v1);
                } else {
                    __half h2[2];
                    h2[0] = __float2half_rn(v0);
                    h2[1] = __float2half_rn(v1);
                    *(unsigned*)(Chi + off) = *(unsigned*)h2;
                }
            }
        }
    }
}

// ---------------------------------------------------------------------------
// Fused QKV GEMM: cols [0,1024)->q fp16-hi, [1024,2048)->k fp16 hi+lo,
// [2048,3072)->v fp32.
__global__ __launch_bounds__(256, 1) void hmma_qkv(
    const __half* __restrict__ Ahi,
    const __half* __restrict__ Bhi, const __half* __restrict__ Blo,
    const float* __restrict__ bq, const float* __restrict__ bk,
    const float* __restrict__ bv,
    __half* __restrict__ qH,
    __half* __restrict__ kH, __half* __restrict__ kL,
    float* __restrict__ vO)
{
    extern __shared__ __align__(128) char smem[];
    const int K = DD;
    constexpr int BLO = 1;

    const int tid  = threadIdx.x;
    const int lane = tid & 31;
    const int wid  = tid >> 5;
    const int row0 = blockIdx.y * 128;
    const int col0 = blockIdx.x * 256;
    const int m_off = (wid & 1) * 64;
    const int n_off = (wid >> 1) * 64;

    const int sel = col0 >> 10;
    const int lc0 = col0 & 1023;

    const __half* AtH = Ahi + (long long)row0 * K;
    const __half* BtH = Bhi + (long long)col0 * K;
    const __half* BtL = Blo + (long long)col0 * K;

    float acc[4][8][4];
    #pragma unroll
    for (int mi = 0; mi < 4; mi++)
        #pragma unroll
        for (int ni = 0; ni < 8; ni++)
            #pragma unroll
            for (int j = 0; j < 4; j++) acc[mi][ni][j] = 0.f;

    const int NC = K / 64;
    GEMM_MAINLOOP(NC, 0)

    const float* bias = (sel == 0) ? bq : (sel == 1) ? bk : bv;

    #pragma unroll
    for (int mi = 0; mi < 4; mi++) {
        #pragma unroll
        for (int ni = 0; ni < 8; ni++) {
            int r_base = row0 + m_off + mi * 16 + (lane >> 2);
            int lc     = lc0 + n_off + ni * 8 + 2 * (lane & 3);
            #pragma unroll
            for (int hh = 0; hh < 2; hh++) {
                int r = r_base + hh * 8;
                float v0 = acc[mi][ni][2 * hh] + bias[lc];
                float v1 = acc[mi][ni][2 * hh + 1] + bias[lc + 1];
                long long off = (long long)r * DD + lc;
                if (sel == 2) {
                    *(float2*)(vO + off) = make_float2(v0, v1);
                } else if (sel == 0) {
                    __half h2[2];
                    h2[0] = __float2half_rn(v0);
                    h2[1] = __float2half_rn(v1);
                    *(unsigned*)(qH + off) = *(unsigned*)h2;
                } else {
                    __half h2[2], l2[2];
                    h2[0] = __float2half_rn(v0);
                    h2[1] = __float2half_rn(v1);
                    l2[0] = __float2half_rn(v0 - __half2float(h2[0]));
                    l2[1] = __float2half_rn(v1 - __half2float(h2[1]));
                    *(unsigned*)(kH + off) = *(unsigned*)h2;
                    *(unsigned*)(kL + off) = *(unsigned*)l2;
                }
            }
        }
    }
}

// ---------------------------------------------------------------------------
__global__ __launch_bounds__(256) void softmax_kernel(
    const float* __restrict__ sc, __half* __restrict__ oH)
{
    const float* p = sc + (long long)blockIdx.x * SS;
    __half* pH = oH + (long long)blockIdx.x * SS;
    const int t = threadIdx.x;
    const int lane = t & 31, warp = t >> 5;
    __shared__ float red[8];

    float v[8];
    float m = NEG_INF;
    #pragma unroll
    for (int i = 0; i < 8; i++) { v[i] = p[t + 256 * i]; m = fmaxf(m, v[i]); }
    #pragma unroll
    for (int o = 16; o > 0; o >>= 1) m = fmaxf(m, __shfl_xor_sync(0xffffffffu, m, o));
    if (lane == 0) red[warp] = m;
    __syncthreads();
    float mb = red[0];
    #pragma unroll
    for (int w = 1; w < 8; w++) mb = fmaxf(mb, red[w]);

    float s = 0.f;
    #pragma unroll
    for (int i = 0; i < 8; i++) { v[i] = __expf(v[i] - mb); s += v[i]; }
    #pragma unroll
    for (int o = 16; o > 0; o >>= 1) s += __shfl_xor_sync(0xffffffffu, s, o);
    __syncthreads();
    if (lane == 0) red[warp] = s;
    __syncthreads();
    float sb = 0.f;
    #pragma unroll
    for (int w = 0; w < 8; w++) sb += red[w];

    float inv = 1.f / sb;
    #pragma unroll
    for (int i = 0; i < 8; i++)
        pH[t + 256 * i] = __float2half_rn(v[i] * inv);
}

// ---------------------------------------------------------------------------
extern "C" void kernel_launch(void* const* d_in, const int* in_sizes, int n_in,
                              void* d_out, int out_size)
{
    const void*  x    = d_in[0];
    const float* emb  = (const float*)d_in[1];
    const float* pos  = (const float*)d_in[2];
    const float* wq   = (const float*)d_in[3];
    const float* bq   = (const float*)d_in[4];
    const float* wk   = (const float*)d_in[5];
    const float* bk   = (const float*)d_in[6];
    const float* wv   = (const float*)d_in[7];
    const float* bv   = (const float*)d_in[8];
    const float* w1s  = (const float*)d_in[9];
    const float* b1s  = (const float*)d_in[10];
    const float* w2s  = (const float*)d_in[11];
    const float* b2s  = (const float*)d_in[12];
    float* out = (float*)d_out;

    cudaFuncSetAttribute(hmma_qkv,           cudaFuncAttributeMaxDynamicSharedMemorySize, SMEM_DYN);
    cudaFuncSetAttribute(hmma_gemm<2,0,0,1>, cudaFuncAttributeMaxDynamicSharedMemorySize, SMEM_DYN);
    cudaFuncSetAttribute(hmma_gemm<1,1,1,1>, cudaFuncAttributeMaxDynamicSharedMemorySize, SMEM_DYN);
    cudaFuncSetAttribute(hmma_gemm<1,1,0,0>, cudaFuncAttributeMaxDynamicSharedMemorySize, SMEM_DYN);
    cudaFuncSetAttribute(hmma_gemm<1,1,0,1>, cudaFuncAttributeMaxDynamicSharedMemorySize, SMEM_DYN);
    cudaFuncSetAttribute(hmma_gemm<1,0,0,1>, cudaFuncAttributeMaxDynamicSharedMemorySize, SMEM_DYN);

    #define SYM(T, n) T* n; { void* p_; cudaGetSymbolAddress(&p_, g_##n); n = (T*)p_; }
    SYM(__half, hH)
    SYM(__half, qH)
    SYM(__half, kH)   SYM(__half, kL)
    SYM(__half, vTH)  SYM(__half, vTL)
    SYM(__half, scH)
    SYM(__half, midH)
    SYM(__half, wqkvH) SYM(__half, wqkvL)
    SYM(__half, w1H)
    SYM(__half, w2H)  SYM(__half, w2L)
    SYM(float, v)  SYM(float, sc)
    #undef SYM

    dim3 tb(32, 8);
    detect_kernel<<<1, 256>>>(x);
    embed_kernel<<<ROWS, 256>>>(x, emb, pos, hH);
    qkvw_transcvt_kernel<<<dim3(32, 32, 3), tb>>>(wq, wk, wv, wqkvH, wqkvL);
    // w1: hi only (FFN1 runs 1-MMA)
    transcvt_kernel<<<dim3(128, 32, LL), tb>>>(w1s, w1H, w1H, DD, MM,
        (long long)DD * MM, (long long)DD * MM, 0);
    transcvt_kernel<<<dim3(32, 128, LL), tb>>>(w2s, w2H, w2L, MM, DD,
        (long long)MM * DD, (long long)MM * DD, 1);

    // Fused QKV: grid (12,64) = 768 CTAs
    hmma_qkv<<<dim3(12, 64, 1), 256, SMEM_DYN>>>(hH, wqkvH, wqkvL,
        bq, bk, bv, qH, kH, kL, v);

    // scores = q @ k^T / 32, anti-causal mask; fully-masked tiles early-exit
    hmma_gemm<2,0,0,1><<<dim3(8, 16, BB), 256, SMEM_DYN>>>(qH, kH, kL, nullptr,
        sc, nullptr, SS, SS, DD,
        (long long)SS * DD, (long long)SS * DD, (long long)SS * SS, 0.03125f);

    transcvt_kernel<<<dim3(32, 64, BB), tb>>>(v, vTH, vTL, SS, DD,
        (long long)SS * DD, (long long)DD * SS, 1);

    softmax_kernel<<<ROWS, 256>>>(sc, scH);

    // h = relu(attn @ v): attn rows exactly 0 for k < row0 -> TRIM=1
    hmma_gemm<1,1,1,1><<<dim3(4, 16, BB), 256, SMEM_DYN>>>(scH, vTH, vTL, nullptr,
        nullptr, hH, SS, DD, SS,
        (long long)SS * SS, (long long)DD * SS, (long long)SS * DD, 0.f);

    // FFN stack: FFN1 = 1-MMA (BLO=0), FFN2 = 2-MMA (BLO=1)
    for (int l = 0; l < LL; l++) {
        hmma_gemm<1,1,0,0><<<dim3(16, 64, 1), 256, SMEM_DYN>>>(
            hH, w1H + (long long)l * DD * MM, w1H + (long long)l * DD * MM,
            b1s + (long long)l * MM, nullptr, midH,
            ROWS, MM, DD, 0, 0, 0, 0.f);
        if (l == LL - 1) {
            hmma_gemm<1,0,0,1><<<dim3(4, 64, 1), 256, SMEM_DYN>>>(
                midH, w2H + (long long)l * MM * DD, w2L + (long long)l * MM * DD,
                b2s + (long long)l * DD, out, nullptr,
                ROWS, DD, MM, 0, 0, 0, 0.f);
        } else {
            hmma_gemm<1,1,0,1><<<dim3(4, 64, 1), 256, SMEM_DYN>>>(
                midH, w2H + (long long)l * MM * DD, w2L + (long long)l * MM * DD,
                b2s + (long long)l * DD, nullptr, hH,
                ROWS, DD, MM, 0, 0, 0, 0.f);
        }
    }
}

// round 16
// speedup vs baseline: 1.1368x; 1.1368x over previous
#include <cuda_runtime.h>
#include <cuda_fp16.h>
#include <cstdint>

// Problem constants
#define BB 4
#define SS 2048
#define DD 1024
#define MM 4096
#define LL 4
#define ROWS (BB*SS)          // 8192
#define NEG_INF __int_as_float(0xff800000)

// GEMM tiling: 128x256 block tile, BK=64, 256 threads (8 warps 2x4, warp 64x64)
// fp16 split: A hi-only, B hi(+optional lo, template BLO).
#define SA 72                 // smem row stride (fp16) = 144B, conflict-free
#define ATILE 18432           // 128*SA*2
#define BTILE 36864           // 256*SA*2
#define STAGE (ATILE + 2*BTILE)     // 92160
#define NSTG 2
#define SMEM_DYN (NSTG*STAGE)       // 184320

// ---------------- scratch (device globals; no allocation allowed) ----------
__device__ __half g_hH[ROWS*DD];
__device__ __half g_qH[ROWS*DD];
__device__ __half g_kH[ROWS*DD],  g_kL[ROWS*DD];
__device__ __half g_vTH[ROWS*DD], g_vTL[ROWS*DD];
__device__ __half g_scH[BB*SS*SS];
__device__ __half g_midH[(long long)ROWS*MM];
__device__ __half g_wqkvH[3*DD*DD], g_wqkvL[3*DD*DD];
__device__ __half g_w1H[LL*DD*MM];                 // FFN1 weights: hi only (1-MMA)
__device__ __half g_w2H[LL*DD*MM], g_w2L[LL*DD*MM];
__device__ float g_v[ROWS*DD];
__device__ float g_sc[BB*SS*SS];
__device__ int   g_is32;

// ---------------------------------------------------------------------------
__global__ void detect_kernel(const void* __restrict__ x) {
    const long long* p = (const long long*)x;
    int bad = 0;
    for (int i = threadIdx.x; i < 4096; i += 256) {
        long long v = p[i];
        if (v < 0 || v >= 32000) bad = 1;
    }
    bad = __syncthreads_or(bad);
    if (threadIdx.x == 0) g_is32 = bad;
}

// h = emb[x] + pos -> fp16 (hi only; h is always an A operand)
__global__ __launch_bounds__(256) void embed_kernel(
    const void* __restrict__ x, const float* __restrict__ emb,
    const float* __restrict__ pos, __half* __restrict__ hH)
{
    int row = blockIdx.x;
    int s = row & (SS - 1);
    long long tok;
    if (g_is32) tok = ((const int*)x)[row];
    else        tok = ((const long long*)x)[row];
    int t = threadIdx.x;
    float4 a = ((const float4*)(emb + tok * (long long)DD))[t];
    float4 b = ((const float4*)(pos + (long long)s * DD))[t];
    __half h4[4];
    h4[0] = __float2half_rn(a.x + b.x);
    h4[1] = __float2half_rn(a.y + b.y);
    h4[2] = __float2half_rn(a.z + b.z);
    h4[3] = __float2half_rn(a.w + b.w);
    *(uint2*)(hH + (long long)row * DD + 4 * t) = *(uint2*)h4;
}

// ---------------------------------------------------------------------------
// Transpose + split: fp32 [R,C] row-major -> fp16 hi (+lo if wlo) [C,R].
__global__ __launch_bounds__(256) void transcvt_kernel(
    const float* __restrict__ in,
    __half* __restrict__ oH, __half* __restrict__ oL,
    int R, int C, long long si, long long so, int wlo)
{
    __shared__ float t[32][33];
    in += (long long)blockIdx.z * si;
    oH += (long long)blockIdx.z * so;
    oL += (long long)blockIdx.z * so;
    int x  = blockIdx.x * 32 + threadIdx.x;
    int y0 = blockIdx.y * 32 + threadIdx.y;
    #pragma unroll
    for (int j = 0; j < 32; j += 8)
        t[threadIdx.y + j][threadIdx.x] = in[(long long)(y0 + j) * C + x];
    __syncthreads();
    int x2 = blockIdx.y * 32 + threadIdx.x;
    int y2 = blockIdx.x * 32 + threadIdx.y;
    #pragma unroll
    for (int j = 0; j < 32; j += 8) {
        float v = t[threadIdx.x][threadIdx.y + j];
        __half h = __float2half_rn(v);
        oH[(long long)(y2 + j) * R + x2] = h;
        if (wlo) {
            __half l = __float2half_rn(v - __half2float(h));
            oL[(long long)(y2 + j) * R + x2] = l;
        }
    }
}

// QKV weight transpose+split in ONE launch (z selects wq/wk/wv).
__global__ __launch_bounds__(256) void qkvw_transcvt_kernel(
    const float* __restrict__ wq, const float* __restrict__ wk,
    const float* __restrict__ wv,
    __half* __restrict__ oH, __half* __restrict__ oL)
{
    __shared__ float t[32][33];
    const float* in = (blockIdx.z == 0) ? wq : (blockIdx.z == 1) ? wk : wv;
    oH += (long long)blockIdx.z * DD * DD;
    oL += (long long)blockIdx.z * DD * DD;
    int x  = blockIdx.x * 32 + threadIdx.x;
    int y0 = blockIdx.y * 32 + threadIdx.y;
    #pragma unroll
    for (int j = 0; j < 32; j += 8)
        t[threadIdx.y + j][threadIdx.x] = in[(long long)(y0 + j) * DD + x];
    __syncthreads();
    int x2 = blockIdx.y * 32 + threadIdx.x;
    int y2 = blockIdx.x * 32 + threadIdx.y;
    #pragma unroll
    for (int j = 0; j < 32; j += 8) {
        float v = t[threadIdx.x][threadIdx.y + j];
        __half h = __float2half_rn(v);
        __half l = __float2half_rn(v - __half2float(h));
        oH[(long long)(y2 + j) * DD + x2] = h;
        oL[(long long)(y2 + j) * DD + x2] = l;
    }
}

// ---------------------------------------------------------------------------
__device__ __forceinline__ unsigned cvta_s(const void* p) {
    return (unsigned)__cvta_generic_to_shared(p);
}
__device__ __forceinline__ void cpa16(unsigned s, const void* g) {
    asm volatile("cp.async.cg.shared.global [%0], [%1], 16;" :: "r"(s), "l"(g));
}
__device__ __forceinline__ void ldsm4(unsigned addr, unsigned* r) {
    asm volatile("ldmatrix.sync.aligned.m8n8.x4.shared.b16 {%0,%1,%2,%3},[%4];"
                 : "=r"(r[0]), "=r"(r[1]), "=r"(r[2]), "=r"(r[3]) : "r"(addr));
}
__device__ __forceinline__ void mma_f16(float* c, const unsigned* a,
                                        unsigned b0, unsigned b1) {
    asm volatile(
        "mma.sync.aligned.m16n8k16.row.col.f32.f16.f16.f32 "
        "{%0,%1,%2,%3},{%4,%5,%6,%7},{%8,%9},{%0,%1,%2,%3};"
        : "+f"(c[0]), "+f"(c[1]), "+f"(c[2]), "+f"(c[3])
        : "r"(a[0]), "r"(a[1]), "r"(a[2]), "r"(a[3]), "r"(b0), "r"(b1));
}

// Inner MMA block: ah*bh (+ ah*bl when BLO). BLO is a constexpr in scope.
#define MMA_BLOCK(acc, ah, bh_cur, bl_cur)                                    \
    {                                                                         \
        _Pragma("unroll")                                                     \
        for (int half = 0; half < 2; half++)                                  \
            _Pragma("unroll")                                                 \
            for (int mi = 0; mi < 4; mi++)                                    \
                mma_f16(acc[mi][np * 2 + half], ah[mi],                       \
                        bh_cur[half * 2], bh_cur[half * 2 + 1]);              \
        if (BLO) {                                                            \
            _Pragma("unroll")                                                 \
            for (int half = 0; half < 2; half++)                              \
                _Pragma("unroll")                                             \
                for (int mi = 0; mi < 4; mi++)                                \
                    mma_f16(acc[mi][np * 2 + half], ah[mi],                   \
                            bl_cur[half * 2], bl_cur[half * 2 + 1]);          \
        }                                                                     \
    }

// Shared mainloop, BK=64, 2-stage single-sync pipeline (round-12 scheme):
//   wait(ch) -> sync -> issue load(ch+1) -> compute(ch)
#define GEMM_MAINLOOP(NCv, CH0v)                                              \
    auto load_stage = [&](int s, int k0) {                                    \
        unsigned sb = cvta_s(smem + s * STAGE);                               \
        int rr = tid >> 3, cc = tid & 7;                                      \
        _Pragma("unroll")                                                     \
        for (int i = 0; i < 4; i++) {                                         \
            int r = rr + 32 * i;                                              \
            long long go = (long long)r * K + k0 + 8 * cc;                    \
            unsigned so = (unsigned)(r * 144 + cc * 16);                      \
            cpa16(sb + so, AtH + go);                                         \
        }                                                                     \
        _Pragma("unroll")                                                     \
        for (int i = 0; i < 8; i++) {                                         \
            int r = rr + 32 * i;                                              \
            long long go = (long long)r * K + k0 + 8 * cc;                    \
            unsigned so = (unsigned)(r * 144 + cc * 16);                      \
            cpa16(sb + ATILE + so, BtH + go);                                 \
            if (BLO) cpa16(sb + ATILE + BTILE + so, BtL + go);                \
        }                                                                     \
        asm volatile("cp.async.commit_group;");                               \
    };                                                                        \
    load_stage(0, (CH0v) * 64);                                               \
    for (int ch = (CH0v); ch < (NCv); ch++) {                                 \
        const int s = (ch - (CH0v)) & 1;                                      \
        asm volatile("cp.async.wait_group 0;");                               \
        __syncthreads();                                                      \
        if (ch + 1 < (NCv)) load_stage(s ^ 1, (ch + 1) * 64);                 \
        const __half* As_hi = (const __half*)(smem + s * STAGE);              \
        const __half* Bs_hi = (const __half*)(smem + s * STAGE + ATILE);      \
        const __half* Bs_lo = (const __half*)(smem + s * STAGE + ATILE + BTILE);\
        const int g = lane >> 3;                                              \
        const int brow_base = n_off + ((g >> 1) << 3) + (lane & 7);           \
        _Pragma("unroll")                                                     \
        for (int ks = 0; ks < 4; ks++) {                                      \
            const int kel_b = ks * 16 + ((g & 1) << 3);                       \
            unsigned ah[4][4];                                                \
            _Pragma("unroll")                                                 \
            for (int mi = 0; mi < 4; mi++) {                                  \
                int rrow = m_off + mi * 16 + (lane & 15);                     \
                int kel  = ((lane >> 4) << 3) + ks * 16;                      \
                ldsm4(cvta_s(As_hi + rrow * SA + kel), ah[mi]);               \
            }                                                                 \
            unsigned bh[2][4], bl[2][4];                                      \
            ldsm4(cvta_s(Bs_hi + brow_base * SA + kel_b), bh[0]);             \
            if (BLO) ldsm4(cvta_s(Bs_lo + brow_base * SA + kel_b), bl[0]);    \
            _Pragma("unroll")                                                 \
            for (int np = 0; np < 4; np++) {                                  \
                const int cur = np & 1, nxt = cur ^ 1;                        \
                if (np < 3) {                                                 \
                    ldsm4(cvta_s(Bs_hi + (brow_base + (np + 1) * 16) * SA + kel_b), bh[nxt]);\
                    if (BLO) ldsm4(cvta_s(Bs_lo + (brow_base + (np + 1) * 16) * SA + kel_b), bl[nxt]);\
                }                                                             \
                MMA_BLOCK(acc, ah, bh[cur], bl[cur])                          \
            }                                                                 \
        }                                                                     \
    }

// ---------------------------------------------------------------------------
// HMMA GEMM, TN: C[M,N] = A[M,K] @ B[N,K]^T. 128x256 tile, 256 threads,
// warp tile 64x64. A fp16 (hi only), B fp16 hi (+lo when BLO=1).
// EPI:  0 = +bias, 1 = +bias(+opt null)+relu, 2 = scale + anti-causal mask
//       (EPI 2 fully-masked tiles exit WITHOUT storing; softmax is mask-aware)
// OUTM: 0 = fp32 C, 1 = fp16 hi-only (Chi)
// TRIM: 1 = start K loop at row0 (A cols exactly zero for k < row0)
// BLO:  1 = 2-MMA split (B hi+lo), 0 = 1-MMA plain fp16 B
template<int EPI, int OUTM, int TRIM, int BLO>
__global__ __launch_bounds__(256, 1) void hmma_gemm(
    const __half* __restrict__ Ahi,
    const __half* __restrict__ Bhi, const __half* __restrict__ Blo,
    const float* __restrict__ bias, float* __restrict__ C,
    __half* __restrict__ Chi,
    int M, int N, int K,
    long long sA, long long sB, long long sC, float scale)
{
    extern __shared__ __align__(128) char smem[];

    const long long zC = (long long)blockIdx.z * sC;
    const int tid  = threadIdx.x;
    const int lane = tid & 31;
    const int wid  = tid >> 5;
    const int row0 = blockIdx.y * 128;
    const int col0 = blockIdx.x * 256;
    const int m_off = (wid & 1) * 64;
    const int n_off = (wid >> 1) * 64;

    // Fully-masked scores tile: softmax reconstructs the mask from indices,
    // so no stores are needed at all.
    if (EPI == 2 && col0 + 256 <= row0) return;

    const long long zA = (long long)blockIdx.z * sA;
    const long long zB = (long long)blockIdx.z * sB;
    const __half* AtH = Ahi + zA + (long long)row0 * K;
    const __half* BtH = Bhi + zB + (long long)col0 * K;
    const __half* BtL = Blo + zB + (long long)col0 * K;

    float acc[4][8][4];
    #pragma unroll
    for (int mi = 0; mi < 4; mi++)
        #pragma unroll
        for (int ni = 0; ni < 8; ni++)
            #pragma unroll
            for (int j = 0; j < 4; j++) acc[mi][ni][j] = 0.f;

    const int NC  = K / 64;
    const int ch0 = TRIM ? (row0 >> 6) : 0;

    GEMM_MAINLOOP(NC, ch0)

    const bool has_bias = (bias != nullptr);
    #pragma unroll
    for (int mi = 0; mi < 4; mi++) {
        #pragma unroll
        for (int ni = 0; ni < 8; ni++) {
            int r_base = row0 + m_off + mi * 16 + (lane >> 2);
            int c      = col0 + n_off + ni * 8 + 2 * (lane & 3);
            #pragma unroll
            for (int hh = 0; hh < 2; hh++) {
                int r = r_base + hh * 8;
                float v0 = acc[mi][ni][2 * hh];
                float v1 = acc[mi][ni][2 * hh + 1];
                if (EPI == 2) {
                    v0 *= scale; v1 *= scale;
                    if (c < r)     v0 = NEG_INF;
                    if (c + 1 < r) v1 = NEG_INF;
                } else {
                    if (has_bias) { v0 += bias[c]; v1 += bias[c + 1]; }
                    if (EPI == 1) { v0 = fmaxf(v0, 0.f); v1 = fmaxf(v1, 0.f); }
                }
                long long off = zC + (long long)r * N + c;
                if (OUTM == 0) {
                    *(float2*)(C + off) = make_float2(v0, v1);
                } else {
                    __half h2[2];
                    h2[0] = __float2half_rn(v0);
                    h2[1] = __float2half_rn(v1);
                    *(unsigned*)(Chi + off) = *(unsigned*)h2;
                }
            }
        }
    }
}

// ---------------------------------------------------------------------------
// Fused QKV GEMM: cols [0,1024)->q fp16-hi, [1024,2048)->k fp16 hi+lo,
// [2048,3072)->v fp32.
__global__ __launch_bounds__(256, 1) void hmma_qkv(
    const __half* __restrict__ Ahi,
    const __half* __restrict__ Bhi, const __half* __restrict__ Blo,
    const float* __restrict__ bq, const float* __restrict__ bk,
    const float* __restrict__ bv,
    __half* __restrict__ qH,
    __half* __restrict__ kH, __half* __restrict__ kL,
    float* __restrict__ vO)
{
    extern __shared__ __align__(128) char smem[];
    const int K = DD;
    constexpr int BLO = 1;

    const int tid  = threadIdx.x;
    const int lane = tid & 31;
    const int wid  = tid >> 5;
    const int row0 = blockIdx.y * 128;
    const int col0 = blockIdx.x * 256;
    const int m_off = (wid & 1) * 64;
    const int n_off = (wid >> 1) * 64;

    const int sel = col0 >> 10;
    const int lc0 = col0 & 1023;

    const __half* AtH = Ahi + (long long)row0 * K;
    const __half* BtH = Bhi + (long long)col0 * K;
    const __half* BtL = Blo + (long long)col0 * K;

    float acc[4][8][4];
    #pragma unroll
    for (int mi = 0; mi < 4; mi++)
        #pragma unroll
        for (int ni = 0; ni < 8; ni++)
            #pragma unroll
            for (int j = 0; j < 4; j++) acc[mi][ni][j] = 0.f;

    const int NC = K / 64;
    GEMM_MAINLOOP(NC, 0)

    const float* bias = (sel == 0) ? bq : (sel == 1) ? bk : bv;

    #pragma unroll
    for (int mi = 0; mi < 4; mi++) {
        #pragma unroll
        for (int ni = 0; ni < 8; ni++) {
            int r_base = row0 + m_off + mi * 16 + (lane >> 2);
            int lc     = lc0 + n_off + ni * 8 + 2 * (lane & 3);
            #pragma unroll
            for (int hh = 0; hh < 2; hh++) {
                int r = r_base + hh * 8;
                float v0 = acc[mi][ni][2 * hh] + bias[lc];
                float v1 = acc[mi][ni][2 * hh + 1] + bias[lc + 1];
                long long off = (long long)r * DD + lc;
                if (sel == 2) {
                    *(float2*)(vO + off) = make_float2(v0, v1);
                } else if (sel == 0) {
                    __half h2[2];
                    h2[0] = __float2half_rn(v0);
                    h2[1] = __float2half_rn(v1);
                    *(unsigned*)(qH + off) = *(unsigned*)h2;
                } else {
                    __half h2[2], l2[2];
                    h2[0] = __float2half_rn(v0);
                    h2[1] = __float2half_rn(v1);
                    l2[0] = __float2half_rn(v0 - __half2float(h2[0]));
                    l2[1] = __float2half_rn(v1 - __half2float(h2[1]));
                    *(unsigned*)(kH + off) = *(unsigned*)h2;
                    *(unsigned*)(kL + off) = *(unsigned*)l2;
                }
            }
        }
    }
}

// ---------------------------------------------------------------------------
// Mask-aware softmax: cols < row are known -inf (never stored by scores);
// reconstructed here from indices. Bit-identical to reading stored -inf.
__global__ __launch_bounds__(256) void softmax_kernel(
    const float* __restrict__ sc, __half* __restrict__ oH)
{
    const float* p = sc + (long long)blockIdx.x * SS;
    __half* pH = oH + (long long)blockIdx.x * SS;
    const int row = blockIdx.x & (SS - 1);
    const int t = threadIdx.x;
    const int lane = t & 31, warp = t >> 5;
    __shared__ float red[8];

    float v[8];
    float m = NEG_INF;
    #pragma unroll
    for (int i = 0; i < 8; i++) {
        int col = t + 256 * i;
        v[i] = (col >= row) ? p[col] : NEG_INF;
        m = fmaxf(m, v[i]);
    }
    #pragma unroll
    for (int o = 16; o > 0; o >>= 1) m = fmaxf(m, __shfl_xor_sync(0xffffffffu, m, o));
    if (lane == 0) red[warp] = m;
    __syncthreads();
    float mb = red[0];
    #pragma unroll
    for (int w = 1; w < 8; w++) mb = fmaxf(mb, red[w]);

    float s = 0.f;
    #pragma unroll
    for (int i = 0; i < 8; i++) { v[i] = __expf(v[i] - mb); s += v[i]; }
    #pragma unroll
    for (int o = 16; o > 0; o >>= 1) s += __shfl_xor_sync(0xffffffffu, s, o);
    __syncthreads();
    if (lane == 0) red[warp] = s;
    __syncthreads();
    float sb = 0.f;
    #pragma unroll
    for (int w = 0; w < 8; w++) sb += red[w];

    float inv = 1.f / sb;
    #pragma unroll
    for (int i = 0; i < 8; i++)
        pH[t + 256 * i] = __float2half_rn(v[i] * inv);
}

// ---------------------------------------------------------------------------
extern "C" void kernel_launch(void* const* d_in, const int* in_sizes, int n_in,
                              void* d_out, int out_size)
{
    const void*  x    = d_in[0];
    const float* emb  = (const float*)d_in[1];
    const float* pos  = (const float*)d_in[2];
    const float* wq   = (const float*)d_in[3];
    const float* bq   = (const float*)d_in[4];
    const float* wk   = (const float*)d_in[5];
    const float* bk   = (const float*)d_in[6];
    const float* wv   = (const float*)d_in[7];
    const float* bv   = (const float*)d_in[8];
    const float* w1s  = (const float*)d_in[9];
    const float* b1s  = (const float*)d_in[10];
    const float* w2s  = (const float*)d_in[11];
    const float* b2s  = (const float*)d_in[12];
    float* out = (float*)d_out;

    cudaFuncSetAttribute(hmma_qkv,           cudaFuncAttributeMaxDynamicSharedMemorySize, SMEM_DYN);
    cudaFuncSetAttribute(hmma_gemm<2,0,0,1>, cudaFuncAttributeMaxDynamicSharedMemorySize, SMEM_DYN);
    cudaFuncSetAttribute(hmma_gemm<1,1,1,1>, cudaFuncAttributeMaxDynamicSharedMemorySize, SMEM_DYN);
    cudaFuncSetAttribute(hmma_gemm<1,1,0,0>, cudaFuncAttributeMaxDynamicSharedMemorySize, SMEM_DYN);
    cudaFuncSetAttribute(hmma_gemm<1,1,0,1>, cudaFuncAttributeMaxDynamicSharedMemorySize, SMEM_DYN);
    cudaFuncSetAttribute(hmma_gemm<1,0,0,1>, cudaFuncAttributeMaxDynamicSharedMemorySize, SMEM_DYN);

    #define SYM(T, n) T* n; { void* p_; cudaGetSymbolAddress(&p_, g_##n); n = (T*)p_; }
    SYM(__half, hH)
    SYM(__half, qH)
    SYM(__half, kH)   SYM(__half, kL)
    SYM(__half, vTH)  SYM(__half, vTL)
    SYM(__half, scH)
    SYM(__half, midH)
    SYM(__half, wqkvH) SYM(__half, wqkvL)
    SYM(__half, w1H)
    SYM(__half, w2H)  SYM(__half, w2L)
    SYM(float, v)  SYM(float, sc)
    #undef SYM

    dim3 tb(32, 8);
    detect_kernel<<<1, 256>>>(x);
    embed_kernel<<<ROWS, 256>>>(x, emb, pos, hH);
    qkvw_transcvt_kernel<<<dim3(32, 32, 3), tb>>>(wq, wk, wv, wqkvH, wqkvL);
    // w1: hi only (FFN1 runs 1-MMA)
    transcvt_kernel<<<dim3(128, 32, LL), tb>>>(w1s, w1H, w1H, DD, MM,
        (long long)DD * MM, (long long)DD * MM, 0);
    transcvt_kernel<<<dim3(32, 128, LL), tb>>>(w2s, w2H, w2L, MM, DD,
        (long long)MM * DD, (long long)MM * DD, 1);

    // Fused QKV: grid (12,64) = 768 CTAs
    hmma_qkv<<<dim3(12, 64, 1), 256, SMEM_DYN>>>(hH, wqkvH, wqkvL,
        bq, bk, bv, qH, kH, kL, v);

    // scores = q @ k^T / 32, anti-causal mask; fully-masked tiles skip stores
    hmma_gemm<2,0,0,1><<<dim3(8, 16, BB), 256, SMEM_DYN>>>(qH, kH, kL, nullptr,
        sc, nullptr, SS, SS, DD,
        (long long)SS * DD, (long long)SS * DD, (long long)SS * SS, 0.03125f);

    transcvt_kernel<<<dim3(32, 64, BB), tb>>>(v, vTH, vTL, SS, DD,
        (long long)SS * DD, (long long)DD * SS, 1);

    softmax_kernel<<<ROWS, 256>>>(sc, scH);

    // h = relu(attn @ v): attn rows exactly 0 for k < row0 -> TRIM=1
    hmma_gemm<1,1,1,1><<<dim3(4, 16, BB), 256, SMEM_DYN>>>(scH, vTH, vTL, nullptr,
        nullptr, hH, SS, DD, SS,
        (long long)SS * SS, (long long)DD * SS, (long long)SS * DD, 0.f);

    // FFN stack: FFN1 = 1-MMA; FFN2 = 1-MMA for layers 0-1 (error attenuated
    // by later layers), 2-MMA for layers 2-3 (incl. final output GEMM).
    for (int l = 0; l < LL; l++) {
        hmma_gemm<1,1,0,0><<<dim3(16, 64, 1), 256, SMEM_DYN>>>(
            hH, w1H + (long long)l * DD * MM, w1H + (long long)l * DD * MM,
            b1s + (long long)l * MM, nullptr, midH,
            ROWS, MM, DD, 0, 0, 0, 0.f);
        if (l == LL - 1) {
            hmma_gemm<1,0,0,1><<<dim3(4, 64, 1), 256, SMEM_DYN>>>(
                midH, w2H + (long long)l * MM * DD, w2L + (long long)l * MM * DD,
                b2s + (long long)l * DD, out, nullptr,
                ROWS, DD, MM, 0, 0, 0, 0.f);
        } else if (l < 2) {
            hmma_gemm<1,1,0,0><<<dim3(4, 64, 1), 256, SMEM_DYN>>>(
                midH, w2H + (long long)l * MM * DD, w2H + (long long)l * MM * DD,
                b2s + (long long)l * DD, nullptr, hH,
                ROWS, DD, MM, 0, 0, 0, 0.f);
        } else {
            hmma_gemm<1,1,0,1><<<dim3(4, 64, 1), 256, SMEM_DYN>>>(
                midH, w2H + (long long)l * MM * DD, w2L + (long long)l * MM * DD,
                b2s + (long long)l * DD, nullptr, hH,
                ROWS, DD, MM, 0, 0, 0, 0.f);
        }
    }
}